// round 1
// baseline (speedup 1.0000x reference)
#include <cuda_runtime.h>
#include <math.h>

#define B_TOTAL 16384

// ---------------- scratch (device globals; no allocation allowed) ----------
__device__ float g_h1[B_TOTAL * 6 * 14 * 14];   // after conv1+relu+pool
__device__ float g_h2[B_TOTAL * 400];           // after conv2+relu+pool (flat)
__device__ float g_h3[B_TOTAL * 120];           // after fc1+relu
__device__ float g_h4[B_TOTAL * 84];            // after fc2+relu

// ---------------------------------------------------------------------------
// conv1: x[B,3,32,32] -> relu(maxpool2(conv 5x5, 6ch)) -> [B,6,14,14]
// 3 images per block; thread = (img, oc, pooled_row); weights in registers.
// ---------------------------------------------------------------------------
__global__ __launch_bounds__(256) void conv1_kernel(
    const float* __restrict__ x, const float* __restrict__ w,
    const float* __restrict__ b, float* __restrict__ out, int B)
{
    __shared__ float s_img[3 * 3072];
    __shared__ float s_w[450];
    __shared__ float s_b[6];

    int img0 = blockIdx.x * 3;
    int nimg = B - img0; if (nimg > 3) nimg = 3;

    for (int i = threadIdx.x; i < 450; i += 256) s_w[i] = w[i];
    if (threadIdx.x < 6) s_b[threadIdx.x] = b[threadIdx.x];
    {
        const float* src = x + (size_t)img0 * 3072;
        int total = nimg * 3072;
        for (int i = threadIdx.x; i < total; i += 256) s_img[i] = src[i];
    }
    __syncthreads();

    int t = threadIdx.x;
    if (t >= nimg * 84) return;
    int img = t / 84;
    int r   = t % 84;
    int oc  = r / 14;
    int py  = r % 14;

    const float* im = s_img + img * 3072;
    float wreg[75];
#pragma unroll
    for (int i = 0; i < 75; i++) wreg[i] = s_w[oc * 75 + i];
    float bias = s_b[oc];

    float* orow = out + (size_t)(img0 + img) * 1176 + oc * 196 + py * 14;

    for (int px = 0; px < 14; px++) {
        float a0 = 0.f, a1 = 0.f, a2 = 0.f, a3 = 0.f;
#pragma unroll
        for (int ic = 0; ic < 3; ic++) {
            float p[36];
            const float* ib = im + ic * 1024 + (2 * py) * 32 + 2 * px;
#pragma unroll
            for (int ry = 0; ry < 6; ry++)
#pragma unroll
                for (int rx = 0; rx < 6; rx++)
                    p[ry * 6 + rx] = ib[ry * 32 + rx];
#pragma unroll
            for (int ky = 0; ky < 5; ky++)
#pragma unroll
                for (int kx = 0; kx < 5; kx++) {
                    float wv = wreg[ic * 25 + ky * 5 + kx];
                    a0 += p[ ky      * 6 + kx    ] * wv;
                    a1 += p[ ky      * 6 + kx + 1] * wv;
                    a2 += p[(ky + 1) * 6 + kx    ] * wv;
                    a3 += p[(ky + 1) * 6 + kx + 1] * wv;
                }
        }
        float m = fmaxf(fmaxf(a0, a1), fmaxf(a2, a3));
        orow[px] = fmaxf(m + bias, 0.f);
    }
}

// ---------------------------------------------------------------------------
// conv2: h1[B,6,14,14] -> relu(maxpool2(conv 5x5, 16ch)) -> [B,16,5,5] flat 400
// 3 images per block; thread = (img, oc, pooled_row).
// ---------------------------------------------------------------------------
__global__ __launch_bounds__(256) void conv2_kernel(
    const float* __restrict__ in, const float* __restrict__ w,
    const float* __restrict__ b, float* __restrict__ out, int B)
{
    __shared__ float s_in[3 * 1176];
    __shared__ float s_w[2400];
    __shared__ float s_b[16];

    int img0 = blockIdx.x * 3;
    int nimg = B - img0; if (nimg > 3) nimg = 3;

    for (int i = threadIdx.x; i < 2400; i += 256) s_w[i] = w[i];
    if (threadIdx.x < 16) s_b[threadIdx.x] = b[threadIdx.x];
    {
        const float* src = in + (size_t)img0 * 1176;
        int total = nimg * 1176;
        for (int i = threadIdx.x; i < total; i += 256) s_in[i] = src[i];
    }
    __syncthreads();

    int t = threadIdx.x;
    if (t >= nimg * 80) return;
    int img = t / 80;
    int r   = t % 80;
    int oc  = r / 5;
    int py  = r % 5;

    float acc[20];
#pragma unroll
    for (int i = 0; i < 20; i++) acc[i] = 0.f;

#pragma unroll
    for (int ic = 0; ic < 6; ic++) {
        float wreg[25];
#pragma unroll
        for (int i = 0; i < 25; i++) wreg[i] = s_w[oc * 150 + ic * 25 + i];
        const float* ib = s_in + img * 1176 + ic * 196 + (2 * py) * 14;
#pragma unroll
        for (int px = 0; px < 5; px++) {
            float p[36];
#pragma unroll
            for (int ry = 0; ry < 6; ry++)
#pragma unroll
                for (int rx = 0; rx < 6; rx++)
                    p[ry * 6 + rx] = ib[ry * 14 + 2 * px + rx];
#pragma unroll
            for (int ky = 0; ky < 5; ky++)
#pragma unroll
                for (int kx = 0; kx < 5; kx++) {
                    float wv = wreg[ky * 5 + kx];
                    acc[px * 4 + 0] += p[ ky      * 6 + kx    ] * wv;
                    acc[px * 4 + 1] += p[ ky      * 6 + kx + 1] * wv;
                    acc[px * 4 + 2] += p[(ky + 1) * 6 + kx    ] * wv;
                    acc[px * 4 + 3] += p[(ky + 1) * 6 + kx + 1] * wv;
                }
        }
    }
    float bias = s_b[oc];
    float* obase = out + (size_t)(img0 + img) * 400 + oc * 25 + py * 5;
#pragma unroll
    for (int px = 0; px < 5; px++) {
        float m = fmaxf(fmaxf(acc[px * 4 + 0], acc[px * 4 + 1]),
                        fmaxf(acc[px * 4 + 2], acc[px * 4 + 3]));
        obase[px] = fmaxf(m + bias, 0.f);
    }
}

// ---------------------------------------------------------------------------
// Generic tiled GEMM: C[M,N] = act(A[M,K] @ W[K,N] + bias), 64x64x16 tiles.
// ---------------------------------------------------------------------------
__global__ __launch_bounds__(256) void gemm_bias_relu(
    const float* __restrict__ A, const float* __restrict__ W,
    const float* __restrict__ bias, float* __restrict__ C,
    int M, int N, int K, int doRelu)
{
    __shared__ float As[16][65];
    __shared__ float Ws[16][64];

    int n0 = blockIdx.x * 64;
    int m0 = blockIdx.y * 64;
    int tx = threadIdx.x & 15;
    int ty = threadIdx.x >> 4;

    float acc[4][4];
#pragma unroll
    for (int i = 0; i < 4; i++)
#pragma unroll
        for (int j = 0; j < 4; j++) acc[i][j] = 0.f;

    for (int k0 = 0; k0 < K; k0 += 16) {
#pragma unroll
        for (int q = 0; q < 4; q++) {
            int idx = threadIdx.x + q * 256;
            int m = idx >> 4, kk = idx & 15;
            int gk = k0 + kk;
            As[kk][m] = (gk < K) ? A[(size_t)(m0 + m) * K + gk] : 0.f;
        }
#pragma unroll
        for (int q = 0; q < 4; q++) {
            int idx = threadIdx.x + q * 256;
            int kk = idx >> 6, n = idx & 63;
            int gk = k0 + kk, gn = n0 + n;
            Ws[kk][n] = (gk < K && gn < N) ? W[(size_t)gk * N + gn] : 0.f;
        }
        __syncthreads();
#pragma unroll
        for (int kk = 0; kk < 16; kk++) {
            float a[4], bb[4];
#pragma unroll
            for (int i = 0; i < 4; i++) a[i] = As[kk][ty + 16 * i];
#pragma unroll
            for (int j = 0; j < 4; j++) bb[j] = Ws[kk][tx + 16 * j];
#pragma unroll
            for (int i = 0; i < 4; i++)
#pragma unroll
                for (int j = 0; j < 4; j++) acc[i][j] += a[i] * bb[j];
        }
        __syncthreads();
    }

#pragma unroll
    for (int i = 0; i < 4; i++) {
        int m = m0 + ty + 16 * i;
#pragma unroll
        for (int j = 0; j < 4; j++) {
            int n = n0 + tx + 16 * j;
            if (n < N && m < M) {
                float v = acc[i][j] + bias[n];
                if (doRelu) v = fmaxf(v, 0.f);
                C[(size_t)m * N + n] = v;
            }
        }
    }
}

// ---------------------------------------------------------------------------
// Fused MoE + fc3:
//   x[B,84] -> gate softmax (top-2 of 2 + renorm == softmax) ->
//   y = sum_e c_e * (relu(x@W1_e + b1_e) @ W2_e + b2_e) -> out = y@fc3_w+fc3_b
// 64 tokens per block; hidden (2048) chunked by 64; gate folded into h.
// ---------------------------------------------------------------------------
#define MOE_SMEM_FLOATS (5376 + 4160 + 5376 + 6144 + 64 + 168 + 128 + 168 + 840 + 16)

__global__ __launch_bounds__(256) void moe_fc3_kernel(
    const float* __restrict__ x,      // g_h4 [B,84]
    const float* __restrict__ gate_w, // [84,2]
    const float* __restrict__ w1,     // [2,84,2048]
    const float* __restrict__ b1,     // [2,2048]
    const float* __restrict__ w2,     // [2,2048,84]
    const float* __restrict__ b2,     // [2,84]
    const float* __restrict__ w3,     // [84,10]
    const float* __restrict__ b3,     // [10]
    float* __restrict__ out)          // [B,10]
{
    extern __shared__ float sm[];
    float* x_s  = sm;                 // 64*84
    float* h_s  = x_s  + 5376;        // 64*65 (padded)
    float* w1_s = h_s  + 4160;        // 84*64   (later reused as y_s[64*84])
    float* w2_s = w1_s + 5376;        // 64*96 (padded cols)
    float* sb1  = w2_s + 6144;        // 64
    float* sgw  = sb1  + 64;          // 168
    float* c_s  = sgw  + 168;         // 64*2
    float* sb2  = c_s  + 128;         // 2*84
    float* sw3  = sb2  + 168;         // 840
    float* sb3  = sw3  + 840;         // 10 (+pad)

    int tid = threadIdx.x;
    int t0  = blockIdx.x * 64;

    for (int i = tid; i < 5376; i += 256) x_s[i] = x[(size_t)t0 * 84 + i];
    for (int i = tid; i < 168;  i += 256) sgw[i] = gate_w[i];
    for (int i = tid; i < 168;  i += 256) sb2[i] = b2[i];
    for (int i = tid; i < 840;  i += 256) sw3[i] = w3[i];
    if (tid < 10) sb3[tid] = b3[tid];
    __syncthreads();

    // gate: softmax over 2 logits
    if (tid < 64) {
        float l0 = 0.f, l1 = 0.f;
        const float* xr = x_s + tid * 84;
#pragma unroll 4
        for (int k = 0; k < 84; k++) {
            l0 += xr[k] * sgw[k * 2 + 0];
            l1 += xr[k] * sgw[k * 2 + 1];
        }
        float m = fmaxf(l0, l1);
        float e0 = expf(l0 - m), e1 = expf(l1 - m);
        float inv = 1.f / (e0 + e1);
        c_s[tid * 2 + 0] = e0 * inv;
        c_s[tid * 2 + 1] = e1 * inv;
    }
    __syncthreads();

    int tx = tid & 15, ty = tid >> 4;

    // acc init = combined expert bias2
    float acc[4][6];
#pragma unroll
    for (int i = 0; i < 4; i++) {
        int t = ty + 16 * i;
        float c0 = c_s[t * 2 + 0], c1 = c_s[t * 2 + 1];
#pragma unroll
        for (int j = 0; j < 6; j++) {
            int d = tx + 16 * j;
            acc[i][j] = (d < 84) ? (c0 * sb2[d] + c1 * sb2[84 + d]) : 0.f;
        }
    }

    for (int e = 0; e < 2; e++) {
        const float* w1p = w1 + (size_t)e * 84 * 2048;
        const float* w2p = w2 + (size_t)e * 2048 * 84;
        const float* b1p = b1 + (size_t)e * 2048;
        for (int c = 0; c < 32; c++) {
            int h0 = c * 64;
            __syncthreads();  // prior step2 readers done before overwrite
            for (int i = tid; i < 5376; i += 256) {
                int k = i >> 6, j = i & 63;
                w1_s[i] = w1p[(size_t)k * 2048 + h0 + j];
            }
            for (int i = tid; i < 6144; i += 256) {
                int k = i / 96, d = i % 96;
                w2_s[i] = (d < 84) ? w2p[(size_t)(h0 + k) * 84 + d] : 0.f;
            }
            if (tid < 64) sb1[tid] = b1p[h0 + tid];
            __syncthreads();

            // step1: h = relu(x @ W1chunk + b1) * gate_e   -> h_s[64][64]
            float hv[4][4];
#pragma unroll
            for (int i = 0; i < 4; i++)
#pragma unroll
                for (int j = 0; j < 4; j++) hv[i][j] = 0.f;
            for (int k = 0; k < 84; k++) {
                float a[4], bb[4];
#pragma unroll
                for (int i = 0; i < 4; i++) a[i] = x_s[(ty + 16 * i) * 84 + k];
#pragma unroll
                for (int j = 0; j < 4; j++) bb[j] = w1_s[k * 64 + tx + 16 * j];
#pragma unroll
                for (int i = 0; i < 4; i++)
#pragma unroll
                    for (int j = 0; j < 4; j++) hv[i][j] += a[i] * bb[j];
            }
#pragma unroll
            for (int i = 0; i < 4; i++) {
                int t = ty + 16 * i;
                float ce = c_s[t * 2 + e];
#pragma unroll
                for (int j = 0; j < 4; j++) {
                    int jj = tx + 16 * j;
                    float h = fmaxf(hv[i][j] + sb1[jj], 0.f) * ce;
                    h_s[t * 65 + jj] = h;
                }
            }
            __syncthreads();

            // step2: acc += h_s @ W2chunk
            for (int k = 0; k < 64; k++) {
                float hh[4], ww[6];
#pragma unroll
                for (int i = 0; i < 4; i++) hh[i] = h_s[(ty + 16 * i) * 65 + k];
#pragma unroll
                for (int j = 0; j < 6; j++) ww[j] = w2_s[k * 96 + tx + 16 * j];
#pragma unroll
                for (int i = 0; i < 4; i++)
#pragma unroll
                    for (int j = 0; j < 6; j++) acc[i][j] += hh[i] * ww[j];
            }
        }
    }

    // stash combined MoE output into y_s (reuse w1_s buffer: 84*64 == 64*84)
    float* y_s = w1_s;
    __syncthreads();
#pragma unroll
    for (int i = 0; i < 4; i++) {
        int t = ty + 16 * i;
#pragma unroll
        for (int j = 0; j < 6; j++) {
            int d = tx + 16 * j;
            if (d < 84) y_s[t * 84 + d] = acc[i][j];
        }
    }
    __syncthreads();

    // fc3 epilogue: [64,84] @ [84,10] + b
    for (int o = tid; o < 640; o += 256) {
        int t = o / 10, cc = o % 10;
        float s = sb3[cc];
        const float* yr = y_s + t * 84;
#pragma unroll 4
        for (int d = 0; d < 84; d++) s += yr[d] * sw3[d * 10 + cc];
        out[(size_t)(t0 + t) * 10 + cc] = s;
    }
}

// ---------------------------------------------------------------------------
extern "C" void kernel_launch(void* const* d_in, const int* in_sizes, int n_in,
                              void* d_out, int out_size)
{
    const float* x       = (const float*)d_in[0];
    const float* conv1_w = (const float*)d_in[1];
    const float* conv1_b = (const float*)d_in[2];
    const float* conv2_w = (const float*)d_in[3];
    const float* conv2_b = (const float*)d_in[4];
    const float* fc1_w   = (const float*)d_in[5];
    const float* fc1_b   = (const float*)d_in[6];
    const float* fc2_w   = (const float*)d_in[7];
    const float* fc2_b   = (const float*)d_in[8];
    const float* gate_w  = (const float*)d_in[9];
    const float* exp_w1  = (const float*)d_in[10];
    const float* exp_b1  = (const float*)d_in[11];
    const float* exp_w2  = (const float*)d_in[12];
    const float* exp_b2  = (const float*)d_in[13];
    const float* fc3_w   = (const float*)d_in[14];
    const float* fc3_b   = (const float*)d_in[15];
    float* out = (float*)d_out;

    const int B = B_TOTAL;

    float *h1, *h2, *h3, *h4;
    cudaGetSymbolAddress((void**)&h1, g_h1);
    cudaGetSymbolAddress((void**)&h2, g_h2);
    cudaGetSymbolAddress((void**)&h3, g_h3);
    cudaGetSymbolAddress((void**)&h4, g_h4);

    static bool attr_done = false;
    // (attribute set is idempotent and does no work on the GPU; safe pre-capture
    //  and during capture — but set every call for determinism)
    cudaFuncSetAttribute(moe_fc3_kernel,
                         cudaFuncAttributeMaxDynamicSharedMemorySize,
                         MOE_SMEM_FLOATS * (int)sizeof(float));
    (void)attr_done;

    int convGrid = (B + 2) / 3;
    conv1_kernel<<<convGrid, 256>>>(x, conv1_w, conv1_b, h1, B);
    conv2_kernel<<<convGrid, 256>>>(h1, conv2_w, conv2_b, h2, B);

    dim3 g1(2, B / 64);
    gemm_bias_relu<<<g1, 256>>>(h2, fc1_w, fc1_b, h3, B, 120, 400, 1);
    dim3 g2(2, B / 64);
    gemm_bias_relu<<<g2, 256>>>(h3, fc2_w, fc2_b, h4, B, 84, 120, 1);

    moe_fc3_kernel<<<B / 64, 256, MOE_SMEM_FLOATS * (int)sizeof(float)>>>(
        h4, gate_w, exp_w1, exp_b1, exp_w2, exp_b2, fc3_w, fc3_b, out);
}

// round 2
// speedup vs baseline: 3.2155x; 3.2155x over previous
#include <cuda_runtime.h>
#include <math.h>
#include <stdint.h>

#define B_TOTAL 16384

// ---------------- scratch (device globals; no allocation allowed) ----------
__device__ float g_h1[B_TOTAL * 6 * 14 * 14];   // after conv1+relu+pool
__device__ float g_h2[B_TOTAL * 400];           // after conv2+relu+pool (flat)
__device__ float g_h3[B_TOTAL * 120];           // after fc1+relu
__device__ float g_h4[B_TOTAL * 84];            // after fc2+relu

// ---------------------------------------------------------------------------
// helpers
// ---------------------------------------------------------------------------
__device__ __forceinline__ float to_tf32(float f) {
    uint32_t u;
    asm("cvt.rna.tf32.f32 %0, %1;" : "=r"(u) : "f"(f));
    return __uint_as_float(u);
}

__device__ __forceinline__ void mma_tf32(float c[4],
                                         uint32_t a0, uint32_t a1, uint32_t a2, uint32_t a3,
                                         uint32_t b0, uint32_t b1) {
    asm volatile(
        "mma.sync.aligned.m16n8k8.row.col.f32.tf32.tf32.f32 "
        "{%0,%1,%2,%3}, {%4,%5,%6,%7}, {%8,%9}, {%0,%1,%2,%3};\n"
        : "+f"(c[0]), "+f"(c[1]), "+f"(c[2]), "+f"(c[3])
        : "r"(a0), "r"(a1), "r"(a2), "r"(a3), "r"(b0), "r"(b1));
}

// ---------------------------------------------------------------------------
// conv1 v2: x[B,3,32,32] -> relu(maxpool2(conv 5x5, 6ch)) -> [B,6,14,14]
// 1 image per block, thread = pooled pixel (py,px), all 6 oc per thread.
// Weight reads are warp-uniform -> LDS broadcast; low register pressure.
// ---------------------------------------------------------------------------
__global__ __launch_bounds__(256) void conv1_kernel(
    const float* __restrict__ x, const float* __restrict__ w,
    const float* __restrict__ b, float* __restrict__ out)
{
    __shared__ float s_img[3072];
    __shared__ float s_w[450];
    __shared__ float s_b[8];

    int img = blockIdx.x;
    int tid = threadIdx.x;

    for (int i = tid; i < 450; i += 256) s_w[i] = w[i];
    if (tid < 6) s_b[tid] = b[tid];
    {
        const float* src = x + (size_t)img * 3072;
        for (int i = tid; i < 3072; i += 256) s_img[i] = src[i];
    }
    __syncthreads();

    if (tid >= 196) return;
    int py = tid / 14;
    int px = tid % 14;

    float acc[24];
#pragma unroll
    for (int i = 0; i < 24; i++) acc[i] = 0.f;

#pragma unroll
    for (int ic = 0; ic < 3; ic++) {
        float p[36];
        const float* ib = s_img + ic * 1024 + (2 * py) * 32 + 2 * px;
#pragma unroll
        for (int ry = 0; ry < 6; ry++)
#pragma unroll
            for (int rx = 0; rx < 6; rx++)
                p[ry * 6 + rx] = ib[ry * 32 + rx];
#pragma unroll
        for (int oc = 0; oc < 6; oc++) {
            float wr[25];
#pragma unroll
            for (int i = 0; i < 25; i++) wr[i] = s_w[oc * 75 + ic * 25 + i];
#pragma unroll
            for (int ky = 0; ky < 5; ky++)
#pragma unroll
                for (int kx = 0; kx < 5; kx++) {
                    float wv = wr[ky * 5 + kx];
                    acc[oc * 4 + 0] += p[ ky      * 6 + kx    ] * wv;
                    acc[oc * 4 + 1] += p[ ky      * 6 + kx + 1] * wv;
                    acc[oc * 4 + 2] += p[(ky + 1) * 6 + kx    ] * wv;
                    acc[oc * 4 + 3] += p[(ky + 1) * 6 + kx + 1] * wv;
                }
        }
    }

    float* ob = out + (size_t)img * 1176 + py * 14 + px;
#pragma unroll
    for (int oc = 0; oc < 6; oc++) {
        float m = fmaxf(fmaxf(acc[oc * 4 + 0], acc[oc * 4 + 1]),
                        fmaxf(acc[oc * 4 + 2], acc[oc * 4 + 3]));
        ob[oc * 196] = fmaxf(m + s_b[oc], 0.f);
    }
}

// ---------------------------------------------------------------------------
// conv2: h1[B,6,14,14] -> relu(maxpool2(conv 5x5, 16ch)) -> [B,16,5,5] flat 400
// ---------------------------------------------------------------------------
__global__ __launch_bounds__(256) void conv2_kernel(
    const float* __restrict__ in, const float* __restrict__ w,
    const float* __restrict__ b, float* __restrict__ out, int B)
{
    __shared__ float s_in[3 * 1176];
    __shared__ float s_w[2400];
    __shared__ float s_b[16];

    int img0 = blockIdx.x * 3;
    int nimg = B - img0; if (nimg > 3) nimg = 3;

    for (int i = threadIdx.x; i < 2400; i += 256) s_w[i] = w[i];
    if (threadIdx.x < 16) s_b[threadIdx.x] = b[threadIdx.x];
    {
        const float* src = in + (size_t)img0 * 1176;
        int total = nimg * 1176;
        for (int i = threadIdx.x; i < total; i += 256) s_in[i] = src[i];
    }
    __syncthreads();

    int t = threadIdx.x;
    if (t >= nimg * 80) return;
    int img = t / 80;
    int r   = t % 80;
    int oc  = r / 5;
    int py  = r % 5;

    float acc[20];
#pragma unroll
    for (int i = 0; i < 20; i++) acc[i] = 0.f;

#pragma unroll
    for (int ic = 0; ic < 6; ic++) {
        float wreg[25];
#pragma unroll
        for (int i = 0; i < 25; i++) wreg[i] = s_w[oc * 150 + ic * 25 + i];
        const float* ib = s_in + img * 1176 + ic * 196 + (2 * py) * 14;
#pragma unroll
        for (int px = 0; px < 5; px++) {
            float p[36];
#pragma unroll
            for (int ry = 0; ry < 6; ry++)
#pragma unroll
                for (int rx = 0; rx < 6; rx++)
                    p[ry * 6 + rx] = ib[ry * 14 + 2 * px + rx];
#pragma unroll
            for (int ky = 0; ky < 5; ky++)
#pragma unroll
                for (int kx = 0; kx < 5; kx++) {
                    float wv = wreg[ky * 5 + kx];
                    acc[px * 4 + 0] += p[ ky      * 6 + kx    ] * wv;
                    acc[px * 4 + 1] += p[ ky      * 6 + kx + 1] * wv;
                    acc[px * 4 + 2] += p[(ky + 1) * 6 + kx    ] * wv;
                    acc[px * 4 + 3] += p[(ky + 1) * 6 + kx + 1] * wv;
                }
        }
    }
    float bias = s_b[oc];
    float* obase = out + (size_t)(img0 + img) * 400 + oc * 25 + py * 5;
#pragma unroll
    for (int px = 0; px < 5; px++) {
        float m = fmaxf(fmaxf(acc[px * 4 + 0], acc[px * 4 + 1]),
                        fmaxf(acc[px * 4 + 2], acc[px * 4 + 3]));
        obase[px] = fmaxf(m + bias, 0.f);
    }
}

// ---------------------------------------------------------------------------
// Generic tiled GEMM: C[M,N] = act(A[M,K] @ W[K,N] + bias), 64x64x16 tiles.
// ---------------------------------------------------------------------------
__global__ __launch_bounds__(256) void gemm_bias_relu(
    const float* __restrict__ A, const float* __restrict__ W,
    const float* __restrict__ bias, float* __restrict__ C,
    int M, int N, int K, int doRelu)
{
    __shared__ float As[16][65];
    __shared__ float Ws[16][64];

    int n0 = blockIdx.x * 64;
    int m0 = blockIdx.y * 64;
    int tx = threadIdx.x & 15;
    int ty = threadIdx.x >> 4;

    float acc[4][4];
#pragma unroll
    for (int i = 0; i < 4; i++)
#pragma unroll
        for (int j = 0; j < 4; j++) acc[i][j] = 0.f;

    for (int k0 = 0; k0 < K; k0 += 16) {
#pragma unroll
        for (int q = 0; q < 4; q++) {
            int idx = threadIdx.x + q * 256;
            int m = idx >> 4, kk = idx & 15;
            int gk = k0 + kk;
            As[kk][m] = (gk < K) ? A[(size_t)(m0 + m) * K + gk] : 0.f;
        }
#pragma unroll
        for (int q = 0; q < 4; q++) {
            int idx = threadIdx.x + q * 256;
            int kk = idx >> 6, n = idx & 63;
            int gk = k0 + kk, gn = n0 + n;
            Ws[kk][n] = (gk < K && gn < N) ? W[(size_t)gk * N + gn] : 0.f;
        }
        __syncthreads();
#pragma unroll
        for (int kk = 0; kk < 16; kk++) {
            float a[4], bb[4];
#pragma unroll
            for (int i = 0; i < 4; i++) a[i] = As[kk][ty + 16 * i];
#pragma unroll
            for (int j = 0; j < 4; j++) bb[j] = Ws[kk][tx + 16 * j];
#pragma unroll
            for (int i = 0; i < 4; i++)
#pragma unroll
                for (int j = 0; j < 4; j++) acc[i][j] += a[i] * bb[j];
        }
        __syncthreads();
    }

#pragma unroll
    for (int i = 0; i < 4; i++) {
        int m = m0 + ty + 16 * i;
#pragma unroll
        for (int j = 0; j < 4; j++) {
            int n = n0 + tx + 16 * j;
            if (n < N && m < M) {
                float v = acc[i][j] + bias[n];
                if (doRelu) v = fmaxf(v, 0.f);
                C[(size_t)m * N + n] = v;
            }
        }
    }
}

// ---------------------------------------------------------------------------
// Fused MoE + fc3 with tf32 tensor cores (mma.sync.m16n8k8).
// 64 tokens/block. For each expert e and each 64-wide hidden chunk:
//   GEMM1: H = relu(X @ W1chunk + b1) * gate_e  (64x64x88, tf32)
//   GEMM2: Y += H @ W2chunk                     (64x96x64, tf32, reg-resident)
// then Y += combined b2, then fc3 epilogue.
// smem operands stored [n][k] with pad strides (92 / 68) -> conflict-free LDS.
// ---------------------------------------------------------------------------
#define XS_STRIDE 92
#define HS_STRIDE 68
#define MOE_SMEM_FLOATS (5888 /*X*/ + 5888 /*W1*/ + 4352 /*H*/ + 6528 /*W2*/ \
                         + 64 /*b1*/ + 168 /*gw*/ + 128 /*c*/ + 168 /*b2*/ \
                         + 840 /*w3*/ + 16 /*b3*/)

__global__ __launch_bounds__(256) void moe_fc3_kernel(
    const float* __restrict__ x,      // [B,84]
    const float* __restrict__ gate_w, // [84,2]
    const float* __restrict__ w1,     // [2,84,2048]
    const float* __restrict__ b1,     // [2,2048]
    const float* __restrict__ w2,     // [2,2048,84]
    const float* __restrict__ b2,     // [2,84]
    const float* __restrict__ w3,     // [84,10]
    const float* __restrict__ b3,     // [10]
    float* __restrict__ out)          // [B,10]
{
    extern __shared__ float sm[];
    float* X_s  = sm;                   // [64][92] tf32 (pad 84..91 zero)
    float* W1_s = X_s  + 64 * XS_STRIDE;  // [64 n][92 k] tf32 (k 84..87 zero)
    float* H_s  = W1_s + 64 * XS_STRIDE;  // [64 m][68 k] tf32
    float* W2_s = H_s  + 64 * HS_STRIDE;  // [96 n][68 k] tf32 (n 84..95 zero)
    float* sb1  = W2_s + 96 * HS_STRIDE;  // 64
    float* sgw  = sb1  + 64;              // 168
    float* c_s  = sgw  + 168;             // 64*2 gates
    float* sb2  = c_s  + 128;             // 2*84
    float* sw3  = sb2  + 168;             // 840
    float* sb3  = sw3  + 840;             // 10(+pad)

    int tid = threadIdx.x;
    int t0  = blockIdx.x * 64;

    // ---- load X (fp32 first, for exact-ish gate), constants ----
    for (int i = tid; i < 64 * 84; i += 256) {
        int t = i / 84, k = i % 84;
        X_s[t * XS_STRIDE + k] = x[(size_t)(t0 + t) * 84 + k];
    }
    for (int i = tid; i < 64 * 8; i += 256) {   // zero pad cols 84..91
        int t = i / 8, k = 84 + (i % 8);
        X_s[t * XS_STRIDE + k] = 0.f;
    }
    for (int i = tid; i < 168; i += 256) sgw[i] = gate_w[i];
    for (int i = tid; i < 168; i += 256) sb2[i] = b2[i];
    for (int i = tid; i < 840; i += 256) sw3[i] = w3[i];
    if (tid < 10) sb3[tid] = b3[tid];
    __syncthreads();

    // ---- gate: softmax over 2 logits (== top-2-of-2 + renorm) ----
    if (tid < 64) {
        float l0 = 0.f, l1 = 0.f;
        const float* xr = X_s + tid * XS_STRIDE;
#pragma unroll 4
        for (int k = 0; k < 84; k++) {
            l0 += xr[k] * sgw[k * 2 + 0];
            l1 += xr[k] * sgw[k * 2 + 1];
        }
        float m = fmaxf(l0, l1);
        float e0 = expf(l0 - m), e1 = expf(l1 - m);
        float inv = 1.f / (e0 + e1);
        c_s[tid * 2 + 0] = e0 * inv;
        c_s[tid * 2 + 1] = e1 * inv;
    }
    __syncthreads();

    // ---- convert X in place to tf32 ----
    for (int i = tid; i < 64 * XS_STRIDE; i += 256) X_s[i] = to_tf32(X_s[i]);

    const int lane = tid & 31, wid = tid >> 5;
    const int gid = lane >> 2, tig = lane & 3;
    const int wm  = (wid >> 1) * 16;       // warp M origin (4 warps in M)
    const int wn1 = (wid & 1) * 32;        // GEMM1 warp N origin (2 warps, 32 each)
    const int wn2 = (wid & 1) * 48;        // GEMM2 warp N origin (2 warps, 48 each)

    float accY[6][4];
#pragma unroll
    for (int nb = 0; nb < 6; nb++)
#pragma unroll
        for (int r = 0; r < 4; r++) accY[nb][r] = 0.f;

    for (int e = 0; e < 2; e++) {
        const float* w1p = w1 + (size_t)e * 84 * 2048;
        const float* w2p = w2 + (size_t)e * 2048 * 84;
        const float* b1p = b1 + (size_t)e * 2048;
        for (int c = 0; c < 32; c++) {
            int h0 = c * 64;
            __syncthreads();   // previous GEMM2 done reading W2_s/H_s

            // load W1 chunk -> [n][k], tf32, k 84..87 zero
            for (int i = tid; i < 64 * 88; i += 256) {
                int n = i & 63, k = i >> 6;   // n fast -> coalesced global read
                float v = (k < 84) ? w1p[(size_t)k * 2048 + h0 + n] : 0.f;
                W1_s[n * XS_STRIDE + k] = to_tf32(v);
            }
            // load W2 chunk -> [n(d)][k(h)], tf32, d 84..95 zero
            for (int i = tid; i < 96 * 64; i += 256) {
                int d = i % 96, k = i / 96;   // d fast -> coalesced
                float v = (d < 84) ? w2p[(size_t)(h0 + k) * 84 + d] : 0.f;
                W2_s[d * HS_STRIDE + k] = to_tf32(v);
            }
            if (tid < 64) sb1[tid] = b1p[h0 + tid];
            __syncthreads();

            // ---- GEMM1: accA = X(64x88) @ W1(88x64), warp tile 16x32 ----
            float accA[4][4];
#pragma unroll
            for (int nb = 0; nb < 4; nb++)
#pragma unroll
                for (int r = 0; r < 4; r++) accA[nb][r] = 0.f;

#pragma unroll
            for (int ks = 0; ks < 11; ks++) {
                int k = ks * 8 + tig;
                uint32_t a0 = __float_as_uint(X_s[(wm + gid    ) * XS_STRIDE + k    ]);
                uint32_t a1 = __float_as_uint(X_s[(wm + gid + 8) * XS_STRIDE + k    ]);
                uint32_t a2 = __float_as_uint(X_s[(wm + gid    ) * XS_STRIDE + k + 4]);
                uint32_t a3 = __float_as_uint(X_s[(wm + gid + 8) * XS_STRIDE + k + 4]);
#pragma unroll
                for (int nb = 0; nb < 4; nb++) {
                    int n = wn1 + nb * 8 + gid;
                    uint32_t b0 = __float_as_uint(W1_s[n * XS_STRIDE + k    ]);
                    uint32_t bb1 = __float_as_uint(W1_s[n * XS_STRIDE + k + 4]);
                    mma_tf32(accA[nb], a0, a1, a2, a3, b0, bb1);
                }
            }

            // epilogue: relu + bias1, gate fold, tf32, -> H_s[m][k=n]
            {
                float gl = c_s[(wm + gid    ) * 2 + e];
                float gh = c_s[(wm + gid + 8) * 2 + e];
#pragma unroll
                for (int nb = 0; nb < 4; nb++) {
                    int n = wn1 + nb * 8 + 2 * tig;
                    float ba = sb1[n], bbv = sb1[n + 1];
                    H_s[(wm + gid    ) * HS_STRIDE + n    ] = to_tf32(fmaxf(accA[nb][0] + ba , 0.f) * gl);
                    H_s[(wm + gid    ) * HS_STRIDE + n + 1] = to_tf32(fmaxf(accA[nb][1] + bbv, 0.f) * gl);
                    H_s[(wm + gid + 8) * HS_STRIDE + n    ] = to_tf32(fmaxf(accA[nb][2] + ba , 0.f) * gh);
                    H_s[(wm + gid + 8) * HS_STRIDE + n + 1] = to_tf32(fmaxf(accA[nb][3] + bbv, 0.f) * gh);
                }
            }
            __syncthreads();

            // ---- GEMM2: accY += H(64x64) @ W2(64x96), warp tile 16x48 ----
#pragma unroll
            for (int ks = 0; ks < 8; ks++) {
                int k = ks * 8 + tig;
                uint32_t a0 = __float_as_uint(H_s[(wm + gid    ) * HS_STRIDE + k    ]);
                uint32_t a1 = __float_as_uint(H_s[(wm + gid + 8) * HS_STRIDE + k    ]);
                uint32_t a2 = __float_as_uint(H_s[(wm + gid    ) * HS_STRIDE + k + 4]);
                uint32_t a3 = __float_as_uint(H_s[(wm + gid + 8) * HS_STRIDE + k + 4]);
#pragma unroll
                for (int nb = 0; nb < 6; nb++) {
                    int n = wn2 + nb * 8 + gid;
                    uint32_t b0 = __float_as_uint(W2_s[n * HS_STRIDE + k    ]);
                    uint32_t bb1 = __float_as_uint(W2_s[n * HS_STRIDE + k + 4]);
                    mma_tf32(accY[nb], a0, a1, a2, a3, b0, bb1);
                }
            }
        }
    }

    // ---- Y = accY + combined b2 -> Y_s (reuse W1_s), then fc3 ----
    __syncthreads();
    float* Y_s = W1_s;   // 5888 >= 64*84
    {
        float cl0 = c_s[(wm + gid    ) * 2], cl1 = c_s[(wm + gid    ) * 2 + 1];
        float ch0 = c_s[(wm + gid + 8) * 2], ch1 = c_s[(wm + gid + 8) * 2 + 1];
#pragma unroll
        for (int nb = 0; nb < 6; nb++) {
            int d = wn2 + nb * 8 + 2 * tig;
            if (d < 84) {
                float bc = cl0 * sb2[d] + cl1 * sb2[84 + d];
                float bh = ch0 * sb2[d] + ch1 * sb2[84 + d];
                Y_s[(wm + gid    ) * 84 + d] = accY[nb][0] + bc;
                Y_s[(wm + gid + 8) * 84 + d] = accY[nb][2] + bh;
            }
            if (d + 1 < 84) {
                float bc = cl0 * sb2[d + 1] + cl1 * sb2[84 + d + 1];
                float bh = ch0 * sb2[d + 1] + ch1 * sb2[84 + d + 1];
                Y_s[(wm + gid    ) * 84 + d + 1] = accY[nb][1] + bc;
                Y_s[(wm + gid + 8) * 84 + d + 1] = accY[nb][3] + bh;
            }
        }
    }
    __syncthreads();

    // fc3: [64,84] @ [84,10] + b3
    for (int o = tid; o < 640; o += 256) {
        int t = o / 10, cc = o % 10;
        float s = sb3[cc];
        const float* yr = Y_s + t * 84;
#pragma unroll 4
        for (int d = 0; d < 84; d++) s += yr[d] * sw3[d * 10 + cc];
        out[(size_t)(t0 + t) * 10 + cc] = s;
    }
}

// ---------------------------------------------------------------------------
extern "C" void kernel_launch(void* const* d_in, const int* in_sizes, int n_in,
                              void* d_out, int out_size)
{
    const float* x       = (const float*)d_in[0];
    const float* conv1_w = (const float*)d_in[1];
    const float* conv1_b = (const float*)d_in[2];
    const float* conv2_w = (const float*)d_in[3];
    const float* conv2_b = (const float*)d_in[4];
    const float* fc1_w   = (const float*)d_in[5];
    const float* fc1_b   = (const float*)d_in[6];
    const float* fc2_w   = (const float*)d_in[7];
    const float* fc2_b   = (const float*)d_in[8];
    const float* gate_w  = (const float*)d_in[9];
    const float* exp_w1  = (const float*)d_in[10];
    const float* exp_b1  = (const float*)d_in[11];
    const float* exp_w2  = (const float*)d_in[12];
    const float* exp_b2  = (const float*)d_in[13];
    const float* fc3_w   = (const float*)d_in[14];
    const float* fc3_b   = (const float*)d_in[15];
    float* out = (float*)d_out;

    const int B = B_TOTAL;

    float *h1, *h2, *h3, *h4;
    cudaGetSymbolAddress((void**)&h1, g_h1);
    cudaGetSymbolAddress((void**)&h2, g_h2);
    cudaGetSymbolAddress((void**)&h3, g_h3);
    cudaGetSymbolAddress((void**)&h4, g_h4);

    cudaFuncSetAttribute(moe_fc3_kernel,
                         cudaFuncAttributeMaxDynamicSharedMemorySize,
                         MOE_SMEM_FLOATS * (int)sizeof(float));

    conv1_kernel<<<B, 256>>>(x, conv1_w, conv1_b, h1);
    conv2_kernel<<<(B + 2) / 3, 256>>>(h1, conv2_w, conv2_b, h2, B);

    dim3 g1(2, B / 64);
    gemm_bias_relu<<<g1, 256>>>(h2, fc1_w, fc1_b, h3, B, 120, 400, 1);
    dim3 g2(2, B / 64);
    gemm_bias_relu<<<g2, 256>>>(h3, fc2_w, fc2_b, h4, B, 84, 120, 1);

    moe_fc3_kernel<<<B / 64, 256, MOE_SMEM_FLOATS * (int)sizeof(float)>>>(
        h4, gate_w, exp_w1, exp_b1, exp_w2, exp_b2, fc3_w, fc3_b, out);
}

// round 3
// speedup vs baseline: 4.1937x; 1.3042x over previous
#include <cuda_runtime.h>
#include <math.h>
#include <stdint.h>

#define B_TOTAL 16384

// ---------------- scratch (device globals; no allocation allowed) ----------
__device__ float g_h1[B_TOTAL * 6 * 14 * 14];   // after conv1+relu+pool
__device__ float g_h2[B_TOTAL * 400];           // after conv2+relu+pool (flat)
__device__ float g_h3[B_TOTAL * 120];           // after fc1+relu
__device__ float g_h4[B_TOTAL * 84];            // after fc2+relu

// pre-converted tf32 expert weights, laid out as smem tiles, pads baked in
// W1t: [cc=0..63][n=0..63][k=0..91]  (cc = e*32+c, value = w1[e][k][c*64+n], k>=84 -> 0)
// W2t: [cc=0..63][d=0..95][k=0..67]  (value = w2[e][c*64+k][d], d>=84 or k>=64 -> 0)
#define W1CH 5888   // 64*92
#define W2CH 6528   // 96*68
__device__ float g_w1t[64 * W1CH];
__device__ float g_w2t[64 * W2CH];

// ---------------------------------------------------------------------------
// helpers
// ---------------------------------------------------------------------------
__device__ __forceinline__ float to_tf32(float f) {
    uint32_t u;
    asm("cvt.rna.tf32.f32 %0, %1;" : "=r"(u) : "f"(f));
    return __uint_as_float(u);
}

__device__ __forceinline__ void mma_tf32(float c[4],
                                         uint32_t a0, uint32_t a1, uint32_t a2, uint32_t a3,
                                         uint32_t b0, uint32_t b1) {
    asm volatile(
        "mma.sync.aligned.m16n8k8.row.col.f32.tf32.tf32.f32 "
        "{%0,%1,%2,%3}, {%4,%5,%6,%7}, {%8,%9}, {%0,%1,%2,%3};\n"
        : "+f"(c[0]), "+f"(c[1]), "+f"(c[2]), "+f"(c[3])
        : "r"(a0), "r"(a1), "r"(a2), "r"(a3), "r"(b0), "r"(b1));
}

#define CP16(dst, src) \
    asm volatile("cp.async.cg.shared.global [%0], [%1], 16;\n" \
                 :: "r"(dst), "l"(src))

// ---------------------------------------------------------------------------
// weight pre-pass kernels (run every launch; tiny)
// ---------------------------------------------------------------------------
__global__ __launch_bounds__(256) void prep_w1(const float* __restrict__ w1)
{
    int idx = blockIdx.x * 256 + threadIdx.x;
    if (idx >= 64 * W1CH) return;
    int cc = idx / W1CH;
    int r  = idx % W1CH;
    int n  = r / 92, k = r % 92;
    int e  = cc >> 5, c = cc & 31;
    float v = 0.f;
    if (k < 84) v = to_tf32(w1[((size_t)e * 84 + k) * 2048 + c * 64 + n]);
    g_w1t[idx] = v;
}

__global__ __launch_bounds__(256) void prep_w2(const float* __restrict__ w2)
{
    int idx = blockIdx.x * 256 + threadIdx.x;
    if (idx >= 64 * W2CH) return;
    int cc = idx / W2CH;
    int r  = idx % W2CH;
    int d  = r / 68, k = r % 68;
    int e  = cc >> 5, c = cc & 31;
    float v = 0.f;
    if (d < 84 && k < 64) v = to_tf32(w2[((size_t)e * 2048 + c * 64 + k) * 84 + d]);
    g_w2t[idx] = v;
}

// ---------------------------------------------------------------------------
// conv1: x[B,3,32,32] -> relu(maxpool2(conv 5x5, 6ch)) -> [B,6,14,14]
// ---------------------------------------------------------------------------
__global__ __launch_bounds__(256) void conv1_kernel(
    const float* __restrict__ x, const float* __restrict__ w,
    const float* __restrict__ b, float* __restrict__ out)
{
    __shared__ float s_img[3072];
    __shared__ float s_w[450];
    __shared__ float s_b[8];

    int img = blockIdx.x;
    int tid = threadIdx.x;

    for (int i = tid; i < 450; i += 256) s_w[i] = w[i];
    if (tid < 6) s_b[tid] = b[tid];
    {
        const float* src = x + (size_t)img * 3072;
        for (int i = tid; i < 3072; i += 256) s_img[i] = src[i];
    }
    __syncthreads();

    if (tid >= 196) return;
    int py = tid / 14;
    int px = tid % 14;

    float acc[24];
#pragma unroll
    for (int i = 0; i < 24; i++) acc[i] = 0.f;

#pragma unroll
    for (int ic = 0; ic < 3; ic++) {
        float p[36];
        const float* ib = s_img + ic * 1024 + (2 * py) * 32 + 2 * px;
#pragma unroll
        for (int ry = 0; ry < 6; ry++)
#pragma unroll
            for (int rx = 0; rx < 6; rx++)
                p[ry * 6 + rx] = ib[ry * 32 + rx];
#pragma unroll
        for (int oc = 0; oc < 6; oc++) {
            float wr[25];
#pragma unroll
            for (int i = 0; i < 25; i++) wr[i] = s_w[oc * 75 + ic * 25 + i];
#pragma unroll
            for (int ky = 0; ky < 5; ky++)
#pragma unroll
                for (int kx = 0; kx < 5; kx++) {
                    float wv = wr[ky * 5 + kx];
                    acc[oc * 4 + 0] += p[ ky      * 6 + kx    ] * wv;
                    acc[oc * 4 + 1] += p[ ky      * 6 + kx + 1] * wv;
                    acc[oc * 4 + 2] += p[(ky + 1) * 6 + kx    ] * wv;
                    acc[oc * 4 + 3] += p[(ky + 1) * 6 + kx + 1] * wv;
                }
        }
    }

    float* ob = out + (size_t)img * 1176 + py * 14 + px;
#pragma unroll
    for (int oc = 0; oc < 6; oc++) {
        float m = fmaxf(fmaxf(acc[oc * 4 + 0], acc[oc * 4 + 1]),
                        fmaxf(acc[oc * 4 + 2], acc[oc * 4 + 3]));
        ob[oc * 196] = fmaxf(m + s_b[oc], 0.f);
    }
}

// ---------------------------------------------------------------------------
// conv2: h1[B,6,14,14] -> relu(maxpool2(conv 5x5, 16ch)) -> [B,16,5,5] flat 400
// ---------------------------------------------------------------------------
__global__ __launch_bounds__(256) void conv2_kernel(
    const float* __restrict__ in, const float* __restrict__ w,
    const float* __restrict__ b, float* __restrict__ out, int B)
{
    __shared__ float s_in[3 * 1176];
    __shared__ float s_w[2400];
    __shared__ float s_b[16];

    int img0 = blockIdx.x * 3;
    int nimg = B - img0; if (nimg > 3) nimg = 3;

    for (int i = threadIdx.x; i < 2400; i += 256) s_w[i] = w[i];
    if (threadIdx.x < 16) s_b[threadIdx.x] = b[threadIdx.x];
    {
        const float* src = in + (size_t)img0 * 1176;
        int total = nimg * 1176;
        for (int i = threadIdx.x; i < total; i += 256) s_in[i] = src[i];
    }
    __syncthreads();

    int t = threadIdx.x;
    if (t >= nimg * 80) return;
    int img = t / 80;
    int r   = t % 80;
    int oc  = r / 5;
    int py  = r % 5;

    float acc[20];
#pragma unroll
    for (int i = 0; i < 20; i++) acc[i] = 0.f;

#pragma unroll
    for (int ic = 0; ic < 6; ic++) {
        float wreg[25];
#pragma unroll
        for (int i = 0; i < 25; i++) wreg[i] = s_w[oc * 150 + ic * 25 + i];
        const float* ib = s_in + img * 1176 + ic * 196 + (2 * py) * 14;
#pragma unroll
        for (int px = 0; px < 5; px++) {
            float p[36];
#pragma unroll
            for (int ry = 0; ry < 6; ry++)
#pragma unroll
                for (int rx = 0; rx < 6; rx++)
                    p[ry * 6 + rx] = ib[ry * 14 + 2 * px + rx];
#pragma unroll
            for (int ky = 0; ky < 5; ky++)
#pragma unroll
                for (int kx = 0; kx < 5; kx++) {
                    float wv = wreg[ky * 5 + kx];
                    acc[px * 4 + 0] += p[ ky      * 6 + kx    ] * wv;
                    acc[px * 4 + 1] += p[ ky      * 6 + kx + 1] * wv;
                    acc[px * 4 + 2] += p[(ky + 1) * 6 + kx    ] * wv;
                    acc[px * 4 + 3] += p[(ky + 1) * 6 + kx + 1] * wv;
                }
        }
    }
    float bias = s_b[oc];
    float* obase = out + (size_t)(img0 + img) * 400 + oc * 25 + py * 5;
#pragma unroll
    for (int px = 0; px < 5; px++) {
        float m = fmaxf(fmaxf(acc[px * 4 + 0], acc[px * 4 + 1]),
                        fmaxf(acc[px * 4 + 2], acc[px * 4 + 3]));
        obase[px] = fmaxf(m + bias, 0.f);
    }
}

// ---------------------------------------------------------------------------
// Generic tiled GEMM: C[M,N] = act(A[M,K] @ W[K,N] + bias), 64x64x16 tiles.
// ---------------------------------------------------------------------------
__global__ __launch_bounds__(256) void gemm_bias_relu(
    const float* __restrict__ A, const float* __restrict__ W,
    const float* __restrict__ bias, float* __restrict__ C,
    int M, int N, int K, int doRelu)
{
    __shared__ float As[16][65];
    __shared__ float Ws[16][64];

    int n0 = blockIdx.x * 64;
    int m0 = blockIdx.y * 64;
    int tx = threadIdx.x & 15;
    int ty = threadIdx.x >> 4;

    float acc[4][4];
#pragma unroll
    for (int i = 0; i < 4; i++)
#pragma unroll
        for (int j = 0; j < 4; j++) acc[i][j] = 0.f;

    for (int k0 = 0; k0 < K; k0 += 16) {
#pragma unroll
        for (int q = 0; q < 4; q++) {
            int idx = threadIdx.x + q * 256;
            int m = idx >> 4, kk = idx & 15;
            int gk = k0 + kk;
            As[kk][m] = (gk < K) ? A[(size_t)(m0 + m) * K + gk] : 0.f;
        }
#pragma unroll
        for (int q = 0; q < 4; q++) {
            int idx = threadIdx.x + q * 256;
            int kk = idx >> 6, n = idx & 63;
            int gk = k0 + kk, gn = n0 + n;
            Ws[kk][n] = (gk < K && gn < N) ? W[(size_t)gk * N + gn] : 0.f;
        }
        __syncthreads();
#pragma unroll
        for (int kk = 0; kk < 16; kk++) {
            float a[4], bb[4];
#pragma unroll
            for (int i = 0; i < 4; i++) a[i] = As[kk][ty + 16 * i];
#pragma unroll
            for (int j = 0; j < 4; j++) bb[j] = Ws[kk][tx + 16 * j];
#pragma unroll
            for (int i = 0; i < 4; i++)
#pragma unroll
                for (int j = 0; j < 4; j++) acc[i][j] += a[i] * bb[j];
        }
        __syncthreads();
    }

#pragma unroll
    for (int i = 0; i < 4; i++) {
        int m = m0 + ty + 16 * i;
#pragma unroll
        for (int j = 0; j < 4; j++) {
            int n = n0 + tx + 16 * j;
            if (n < N && m < M) {
                float v = acc[i][j] + bias[n];
                if (doRelu) v = fmaxf(v, 0.f);
                C[(size_t)m * N + n] = v;
            }
        }
    }
}

// ---------------------------------------------------------------------------
// Fused MoE + fc3, tf32 mma, 128 tokens/block, 512 threads.
// Double-buffered cp.async weight pipeline from pre-converted g_w1t/g_w2t.
// ---------------------------------------------------------------------------
#define XS_STRIDE 92
#define HS_STRIDE 68
// smem float offsets
#define OFF_X    0
#define OFF_W1   (128 * XS_STRIDE)                  // 11776
#define OFF_H    (OFF_W1 + 2 * W1CH)                // 23552
#define OFF_W2   (OFF_H + 128 * HS_STRIDE)          // 32256
#define OFF_B1   (OFF_W2 + 2 * W2CH)                // 45312
#define OFF_GW   (OFF_B1 + 128)                     // 45440
#define OFF_C    (OFF_GW + 168)                     // 45608
#define OFF_B2   (OFF_C + 256)                      // 45864
#define OFF_W3   (OFF_B2 + 168)                     // 46032
#define OFF_B3   (OFF_W3 + 840)                     // 46872
#define MOE_SMEM_FLOATS (OFF_B3 + 16)               // 46888

__global__ __launch_bounds__(512) void moe_fc3_kernel(
    const float* __restrict__ x,      // [B,84]
    const float* __restrict__ gate_w, // [84,2]
    const float* __restrict__ b1g,    // [2,2048]
    const float* __restrict__ b2,     // [2,84]
    const float* __restrict__ w3,     // [84,10]
    const float* __restrict__ b3,     // [10]
    float* __restrict__ out)          // [B,10]
{
    extern __shared__ float sm[];
    float* X_s  = sm + OFF_X;
    float* W1_s = sm + OFF_W1;
    float* H_s  = sm + OFF_H;
    float* W2_s = sm + OFF_W2;
    float* sb1  = sm + OFF_B1;
    float* sgw  = sm + OFF_GW;
    float* c_s  = sm + OFF_C;
    float* sb2  = sm + OFF_B2;
    float* sw3  = sm + OFF_W3;
    float* sb3  = sm + OFF_B3;

    const int tid = threadIdx.x;
    const int t0  = blockIdx.x * 128;

    const uint32_t smbase = (uint32_t)__cvta_generic_to_shared(sm);
    const uint32_t w1_sm  = smbase + OFF_W1 * 4;
    const uint32_t w2_sm  = smbase + OFF_W2 * 4;
    const uint32_t b1_sm  = smbase + OFF_B1 * 4;

    // ---- prologue: async-load chunk 0 weights ----
    {
        const float4* s1 = (const float4*)(g_w1t);
        for (int i = tid; i < W1CH / 4; i += 512) CP16(w1_sm + i * 16, s1 + i);
        const float4* s2 = (const float4*)(g_w2t);
        for (int i = tid; i < W2CH / 4; i += 512) CP16(w2_sm + i * 16, s2 + i);
        if (tid < 16) CP16(b1_sm + tid * 16, (const float4*)b1g + tid);
    }
    asm volatile("cp.async.commit_group;\n" ::: "memory");

    // ---- sync loads: X + constants ----
    for (int i = tid; i < 128 * 84; i += 512) {
        int t = i / 84, k = i % 84;
        X_s[t * XS_STRIDE + k] = x[(size_t)(t0 + t) * 84 + k];
    }
    for (int i = tid; i < 128 * 8; i += 512) {
        int t = i / 8, k = 84 + (i % 8);
        X_s[t * XS_STRIDE + k] = 0.f;
    }
    for (int i = tid; i < 168; i += 512) sgw[i] = gate_w[i];
    for (int i = tid; i < 168; i += 512) sb2[i] = b2[i];
    for (int i = tid; i < 840; i += 512) sw3[i] = w3[i];
    if (tid < 10) sb3[tid] = b3[tid];
    __syncthreads();

    // ---- convert X to tf32 in place ----
    for (int i = tid; i < 128 * XS_STRIDE; i += 512) X_s[i] = to_tf32(X_s[i]);
    __syncthreads();

    // ---- gate: softmax over 2 logits (top-2 of 2 + renorm == softmax) ----
    if (tid < 128) {
        float l0 = 0.f, l1 = 0.f;
        const float* xr = X_s + tid * XS_STRIDE;
#pragma unroll 4
        for (int k = 0; k < 84; k++) {
            l0 += xr[k] * sgw[k * 2 + 0];
            l1 += xr[k] * sgw[k * 2 + 1];
        }
        float m = fmaxf(l0, l1);
        float e0 = expf(l0 - m), e1 = expf(l1 - m);
        float inv = 1.f / (e0 + e1);
        c_s[tid * 2 + 0] = e0 * inv;
        c_s[tid * 2 + 1] = e1 * inv;
    }
    // (visibility of c_s covered by the loop-top __syncthreads)

    const int lane = tid & 31, wid = tid >> 5;
    const int gid = lane >> 2, tig = lane & 3;
    const int wm  = (wid >> 1) * 16;       // 8 warp groups in M (0..112)
    const int wn1 = (wid & 1) * 32;        // GEMM1 N split
    const int wn2 = (wid & 1) * 48;        // GEMM2 N split

    float accY[6][4];
#pragma unroll
    for (int nb = 0; nb < 6; nb++)
#pragma unroll
        for (int r = 0; r < 4; r++) accY[nb][r] = 0.f;

    for (int cc = 0; cc < 64; cc++) {
        const int buf = cc & 1;
        const int e   = cc >> 5;

        asm volatile("cp.async.wait_group 0;\n" ::: "memory");
        __syncthreads();

        // prefetch chunk cc+1 into the other buffer (its old data consumed)
        if (cc + 1 < 64) {
            const int nb2 = buf ^ 1;
            const float4* s1 = (const float4*)(g_w1t + (size_t)(cc + 1) * W1CH);
            uint32_t d1 = w1_sm + nb2 * (W1CH * 4);
            for (int i = tid; i < W1CH / 4; i += 512) CP16(d1 + i * 16, s1 + i);
            const float4* s2 = (const float4*)(g_w2t + (size_t)(cc + 1) * W2CH);
            uint32_t d2 = w2_sm + nb2 * (W2CH * 4);
            for (int i = tid; i < W2CH / 4; i += 512) CP16(d2 + i * 16, s2 + i);
            if (tid < 16)
                CP16(b1_sm + nb2 * 256 + tid * 16,
                     (const float4*)(b1g + (size_t)(cc + 1) * 64) + tid);
        }
        asm volatile("cp.async.commit_group;\n" ::: "memory");

        const float* W1b = W1_s + buf * W1CH;
        const float* W2b = W2_s + buf * W2CH;
        const float* b1b = sb1 + buf * 64;

        // ---- GEMM1: accA = X(128x88) @ W1(88x64), warp tile 16x32 ----
        float accA[4][4];
#pragma unroll
        for (int nb = 0; nb < 4; nb++)
#pragma unroll
            for (int r = 0; r < 4; r++) accA[nb][r] = 0.f;

#pragma unroll
        for (int ks = 0; ks < 11; ks++) {
            int k = ks * 8 + tig;
            uint32_t a0 = __float_as_uint(X_s[(wm + gid    ) * XS_STRIDE + k    ]);
            uint32_t a1 = __float_as_uint(X_s[(wm + gid + 8) * XS_STRIDE + k    ]);
            uint32_t a2 = __float_as_uint(X_s[(wm + gid    ) * XS_STRIDE + k + 4]);
            uint32_t a3 = __float_as_uint(X_s[(wm + gid + 8) * XS_STRIDE + k + 4]);
#pragma unroll
            for (int nb = 0; nb < 4; nb++) {
                int n = wn1 + nb * 8 + gid;
                uint32_t b0  = __float_as_uint(W1b[n * XS_STRIDE + k    ]);
                uint32_t bb1 = __float_as_uint(W1b[n * XS_STRIDE + k + 4]);
                mma_tf32(accA[nb], a0, a1, a2, a3, b0, bb1);
            }
        }

        // epilogue: bias + relu + gate fold -> H_s (tf32)
        {
            float gl = c_s[(wm + gid    ) * 2 + e];
            float gh = c_s[(wm + gid + 8) * 2 + e];
#pragma unroll
            for (int nb = 0; nb < 4; nb++) {
                int n = wn1 + nb * 8 + 2 * tig;
                float ba = b1b[n], bbv = b1b[n + 1];
                H_s[(wm + gid    ) * HS_STRIDE + n    ] = to_tf32(fmaxf(accA[nb][0] + ba , 0.f) * gl);
                H_s[(wm + gid    ) * HS_STRIDE + n + 1] = to_tf32(fmaxf(accA[nb][1] + bbv, 0.f) * gl);
                H_s[(wm + gid + 8) * HS_STRIDE + n    ] = to_tf32(fmaxf(accA[nb][2] + ba , 0.f) * gh);
                H_s[(wm + gid + 8) * HS_STRIDE + n + 1] = to_tf32(fmaxf(accA[nb][3] + bbv, 0.f) * gh);
            }
        }
        __syncthreads();

        // ---- GEMM2: accY += H(128x64) @ W2(64x96), warp tile 16x48 ----
#pragma unroll
        for (int ks = 0; ks < 8; ks++) {
            int k = ks * 8 + tig;
            uint32_t a0 = __float_as_uint(H_s[(wm + gid    ) * HS_STRIDE + k    ]);
            uint32_t a1 = __float_as_uint(H_s[(wm + gid + 8) * HS_STRIDE + k    ]);
            uint32_t a2 = __float_as_uint(H_s[(wm + gid    ) * HS_STRIDE + k + 4]);
            uint32_t a3 = __float_as_uint(H_s[(wm + gid + 8) * HS_STRIDE + k + 4]);
#pragma unroll
            for (int nb = 0; nb < 6; nb++) {
                int n = wn2 + nb * 8 + gid;
                uint32_t b0  = __float_as_uint(W2b[n * HS_STRIDE + k    ]);
                uint32_t bb1 = __float_as_uint(W2b[n * HS_STRIDE + k + 4]);
                mma_tf32(accY[nb], a0, a1, a2, a3, b0, bb1);
            }
        }
    }

    // ---- Y = accY + combined b2 -> Y_s (reuse W1_s area), then fc3 ----
    __syncthreads();
    float* Y_s = W1_s;   // 2*5888 >= 128*84
    {
        float cl0 = c_s[(wm + gid    ) * 2], cl1 = c_s[(wm + gid    ) * 2 + 1];
        float ch0 = c_s[(wm + gid + 8) * 2], ch1 = c_s[(wm + gid + 8) * 2 + 1];
#pragma unroll
        for (int nb = 0; nb < 6; nb++) {
            int d = wn2 + nb * 8 + 2 * tig;
            if (d < 84) {
                float bc = cl0 * sb2[d] + cl1 * sb2[84 + d];
                float bh = ch0 * sb2[d] + ch1 * sb2[84 + d];
                Y_s[(wm + gid    ) * 84 + d] = accY[nb][0] + bc;
                Y_s[(wm + gid + 8) * 84 + d] = accY[nb][2] + bh;
            }
            if (d + 1 < 84) {
                float bc = cl0 * sb2[d + 1] + cl1 * sb2[84 + d + 1];
                float bh = ch0 * sb2[d + 1] + ch1 * sb2[84 + d + 1];
                Y_s[(wm + gid    ) * 84 + d + 1] = accY[nb][1] + bc;
                Y_s[(wm + gid + 8) * 84 + d + 1] = accY[nb][3] + bh;
            }
        }
    }
    __syncthreads();

    // fc3: [128,84] @ [84,10] + b3
    for (int o = tid; o < 1280; o += 512) {
        int t = o / 10, cc = o % 10;
        float s = sb3[cc];
        const float* yr = Y_s + t * 84;
#pragma unroll 4
        for (int d = 0; d < 84; d++) s += yr[d] * sw3[d * 10 + cc];
        out[(size_t)(t0 + t) * 10 + cc] = s;
    }
}

// ---------------------------------------------------------------------------
extern "C" void kernel_launch(void* const* d_in, const int* in_sizes, int n_in,
                              void* d_out, int out_size)
{
    const float* x       = (const float*)d_in[0];
    const float* conv1_w = (const float*)d_in[1];
    const float* conv1_b = (const float*)d_in[2];
    const float* conv2_w = (const float*)d_in[3];
    const float* conv2_b = (const float*)d_in[4];
    const float* fc1_w   = (const float*)d_in[5];
    const float* fc1_b   = (const float*)d_in[6];
    const float* fc2_w   = (const float*)d_in[7];
    const float* fc2_b   = (const float*)d_in[8];
    const float* gate_w  = (const float*)d_in[9];
    const float* exp_w1  = (const float*)d_in[10];
    const float* exp_b1  = (const float*)d_in[11];
    const float* exp_w2  = (const float*)d_in[12];
    const float* exp_b2  = (const float*)d_in[13];
    const float* fc3_w   = (const float*)d_in[14];
    const float* fc3_b   = (const float*)d_in[15];
    float* out = (float*)d_out;

    const int B = B_TOTAL;

    float *h1, *h2, *h3, *h4;
    cudaGetSymbolAddress((void**)&h1, g_h1);
    cudaGetSymbolAddress((void**)&h2, g_h2);
    cudaGetSymbolAddress((void**)&h3, g_h3);
    cudaGetSymbolAddress((void**)&h4, g_h4);

    cudaFuncSetAttribute(moe_fc3_kernel,
                         cudaFuncAttributeMaxDynamicSharedMemorySize,
                         MOE_SMEM_FLOATS * (int)sizeof(float));

    // weight pre-pass (independent of conv path; overlaps on GPU)
    prep_w1<<<(64 * W1CH + 255) / 256, 256>>>(exp_w1);
    prep_w2<<<(64 * W2CH + 255) / 256, 256>>>(exp_w2);

    conv1_kernel<<<B, 256>>>(x, conv1_w, conv1_b, h1);
    conv2_kernel<<<(B + 2) / 3, 256>>>(h1, conv2_w, conv2_b, h2, B);

    dim3 g1(2, B / 64);
    gemm_bias_relu<<<g1, 256>>>(h2, fc1_w, fc1_b, h3, B, 120, 400, 1);
    dim3 g2(2, B / 64);
    gemm_bias_relu<<<g2, 256>>>(h3, fc2_w, fc2_b, h4, B, 84, 120, 1);

    moe_fc3_kernel<<<B / 128, 512, MOE_SMEM_FLOATS * (int)sizeof(float)>>>(
        h4, gate_w, exp_b1, exp_b2, fc3_w, fc3_b, out);
}